// round 16
// baseline (speedup 1.0000x reference)
#include <cuda_runtime.h>
#include <cuda_fp16.h>
#include <cstdint>
#include <math.h>

#define B_DIM 1024
#define H_DIM 1024

// fp16 fragment-major blocks, K-chunk = 64:
//   A (m16-block, kchunk64) = 2048 B;  W (n8-block, kchunk64) = 1024 B
#define A_STG 16384                       // 8 m16-blocks (M=128)
#define B_STG 8192                        // 8 n8-blocks (N=64)
#define STAGE_BYTES (A_STG + B_STG)       // 24576
#define NSTAGE 3
#define SMEM_BYTES (NSTAGE * STAGE_BYTES) // 73728 -> 3 CTAs/SM
#define HIDS 68

// fp16 fragment-major operands (K padded 1000 -> 1024 with zeros)
__device__ __half hA_core[B_DIM * 1024];
__device__ __half hA_h[B_DIM * 1024];
__device__ __half hA_concept[B_DIM * 1024];
__device__ __half hW_in[4 * H_DIM * 1024];
__device__ __half hW_st[4 * H_DIM * 1024];
__device__ __half hW_ci[4 * H_DIM * 1024];
__device__ __half hW_cs[4 * H_DIM * 1024];
// inter-phase f32 accumulator spills (bit-exact round trip)
__device__ float g_xi[B_DIM * 4 * H_DIM];
__device__ float g_hs[B_DIM * 4 * H_DIM];
__device__ float g_gi[B_DIM * 4 * H_DIM];

__device__ __forceinline__ uint32_t smem_u32(const void* p) {
    uint32_t a;
    asm("{ .reg .u64 t; cvta.to.shared.u64 t, %1; cvt.u32.u64 %0, t; }" : "=r"(a) : "l"(p));
    return a;
}
__device__ __forceinline__ void cpa16(uint32_t dst, const void* src) {
    asm volatile("cp.async.cg.shared.global [%0], [%1], 16;"
                 :: "r"(dst), "l"(__cvta_generic_to_global(src)) : "memory");
}
#define CP_COMMIT() asm volatile("cp.async.commit_group;" ::: "memory")
#define CP_WAIT1()  asm volatile("cp.async.wait_group 1;" ::: "memory")

__device__ __forceinline__ void mma16(float* d, const uint32_t* a, const uint32_t* b) {
    asm volatile(
        "mma.sync.aligned.m16n8k16.row.col.f32.f16.f16.f32 "
        "{%0,%1,%2,%3}, {%4,%5,%6,%7}, {%8,%9}, {%0,%1,%2,%3};"
        : "+f"(d[0]), "+f"(d[1]), "+f"(d[2]), "+f"(d[3])
        : "r"(a[0]), "r"(a[1]), "r"(a[2]), "r"(a[3]), "r"(b[0]), "r"(b[1]));
}

// Warp tile 32(M) x 32(N), K=64 chunk (4 mma K-steps of 16). 8 HMMA per ks.
__device__ __forceinline__ void cchunk(const char* st, float (&acc)[32],
                                       int wm, int wn, int lane) {
    const char* Ab = st + wm * 2 * 2048 + lane * 16;
    const char* Bb = st + A_STG + wn * 4 * 1024 + lane * 8;
#pragma unroll
    for (int ks = 0; ks < 4; ks++) {
        uint2 bf[4];
#pragma unroll
        for (int nt = 0; nt < 4; nt++)
            bf[nt] = *(const uint2*)(Bb + nt * 1024 + ks * 256);
#pragma unroll
        for (int mt = 0; mt < 2; mt++) {
            uint4 af = *(const uint4*)(Ab + mt * 2048 + ks * 512);
#pragma unroll
            for (int nt = 0; nt < 4; nt++)
                mma16(&acc[(mt * 4 + nt) * 4], (const uint32_t*)&af,
                      (const uint32_t*)&bf[nt]);
        }
    }
}

__global__ void __launch_bounds__(256, 3) scn_mma_kernel(
    const float* __restrict__ c_state, float* __restrict__ out) {
    extern __shared__ char smc[];
    const uint32_t sbase = smem_u32(smc);
    const int tid = threadIdx.x, lane = tid & 31, wid = tid >> 5;
    const int gid = lane >> 2, ctid = lane & 3;
    const int wm = wid >> 1, wn = wid & 1;       // warp grid 4(M) x 2(N)
    const int hcol0 = blockIdx.x * 16;           // 16 h-cols x 4 sections = N 64
    const int brow0 = blockIdx.y * 128;
    const int cta = blockIdx.y * 64 + blockIdx.x;

    auto issue = [&](int g) {
        const int ph = g >> 4, kc = g & 15;
        const __half* A  = (ph == 0) ? hA_core : (ph == 1) ? hA_h : hA_concept;
        const __half* B0 = (ph == 0) ? hW_in : (ph == 1) ? hW_st
                         : (ph == 2) ? hW_ci : hW_cs;
        uint32_t st = sbase + (uint32_t)(((uint32_t)g) % 3u) * STAGE_BYTES;
        const int blk = tid >> 5, sub = tid & 31;
        {   // A: 8 m16-blocks (2048 B each), 64 B/thread
            const __half* s = A + ((size_t)((blockIdx.y * 8 + blk) * 16 + kc)) * 1024 + sub * 32;
            uint32_t d = st + (uint32_t)(blk * 2048 + sub * 64);
#pragma unroll
            for (int i = 0; i < 4; i++) cpa16(d + i * 16, s + i * 8);
        }
        {   // B: 8 n8-blocks (1024 B each), 32 B/thread; blk = sec*2 + jb
            int ntg = ((blk >> 1) << 7) + blockIdx.x * 2 + (blk & 1);
            const __half* s = B0 + ((size_t)(ntg * 16 + kc)) * 512 + sub * 16;
            uint32_t d = st + A_STG + (uint32_t)(blk * 1024 + sub * 32);
            cpa16(d, s);
            cpa16(d + 16, s + 8);
        }
        CP_COMMIT();
    };

#define STEP(g)                                                            \
    CP_WAIT1();                                                            \
    __syncthreads();                                                       \
    if ((g) + 2 < 64) issue((g) + 2); else CP_COMMIT();                    \
    const char* st = smc + (size_t)(((uint32_t)(g)) % 3u) * STAGE_BYTES;

    // per-warp spill region: 8 float4 x 32 lanes (32x32 tile)
    const size_t fragbase = ((size_t)(cta * 8 + wid) * 8) * 32 + lane;

    issue(0); issue(1);

    {   // phase 0: xi = core @ W_in -> spill
        float acc[32] = {};
        for (int g = 0; g < 16; g++) { STEP(g); cchunk(st, acc, wm, wn, lane); }
        float4* sp = (float4*)g_xi;
#pragma unroll
        for (int t = 0; t < 8; t++)
            sp[fragbase + (size_t)t * 32] =
                make_float4(acc[t*4], acc[t*4+1], acc[t*4+2], acc[t*4+3]);
    }
    {   // phase 1: hs = h @ W_st -> spill
        float acc[32] = {};
        for (int g = 16; g < 32; g++) { STEP(g); cchunk(st, acc, wm, wn, lane); }
        float4* sp = (float4*)g_hs;
#pragma unroll
        for (int t = 0; t < 8; t++)
            sp[fragbase + (size_t)t * 32] =
                make_float4(acc[t*4], acc[t*4+1], acc[t*4+2], acc[t*4+3]);
    }
    {   // phase 2: gi = concept @ W_ci -> spill
        float acc[32] = {};
        for (int g = 32; g < 48; g++) { STEP(g); cchunk(st, acc, wm, wn, lane); }
        float4* sp = (float4*)g_gi;
#pragma unroll
        for (int t = 0; t < 8; t++)
            sp[fragbase + (size_t)t * 32] =
                make_float4(acc[t*4], acc[t*4+1], acc[t*4+2], acc[t*4+3]);
    }
    // phase 3: gs = concept @ W_cs (kept in regs)
    float ags[32] = {};
    for (int g = 48; g < 64; g++) { STEP(g); cchunk(st, ags, wm, wn, lane); }
#undef STEP
    __syncthreads();

    // ---- fused epilogue: hidden = sigmoid(gi*xi + gs*hs) staged in smem ----
    float* hid = (float*)smc;   // 128 x HIDS floats (34.8 KB)
    {
        const float4* xs = (const float4*)g_xi;
        const float4* hs = (const float4*)g_hs;
        const float4* gs = (const float4*)g_gi;
#pragma unroll
        for (int t = 0; t < 8; t++) {
            float4 x4 = xs[fragbase + (size_t)t * 32];
            float4 h4 = hs[fragbase + (size_t)t * 32];
            float4 g4 = gs[fragbase + (size_t)t * 32];
            const float zx[4] = {x4.x, x4.y, x4.z, x4.w};
            const float zh[4] = {h4.x, h4.y, h4.z, h4.w};
            const float zg[4] = {g4.x, g4.y, g4.z, g4.w};
            int mt = t >> 2, nt = t & 3;
#pragma unroll
            for (int c = 0; c < 4; c++) {
                float z = zg[c] * zx[c] + ags[t * 4 + c] * zh[c];
                int m = wm * 32 + mt * 16 + gid + ((c >> 1) ? 8 : 0);
                int n = wn * 32 + nt * 8 + ctid * 2 + (c & 1);   // n in 0..63
                hid[m * HIDS + n] = 1.0f / (1.0f + expf(-z));
            }
        }
    }
    __syncthreads();

    // ---- LSTM combine: hid[m][sec*16 + j], secs = i, f, o, c_cand ----
    {
        int m = tid >> 1;
        int j0 = (tid & 1) * 8;
        const float* row = hid + m * HIDS;
        size_t gbase = (size_t)(brow0 + m) * H_DIM + hcol0 + j0;
#pragma unroll
        for (int q = 0; q < 2; q++) {
            float4 hv, cv;
            float* ph = (float*)&hv;
            float* pc = (float*)&cv;
#pragma unroll
            for (int r = 0; r < 4; r++) {
                int j = j0 + q * 4 + r;
                float it = row[j];
                float ft = row[16 + j];
                float ot = row[32 + j];
                float cc = row[48 + j];
                float cs = c_state[gbase - j0 + j];
                float ct = it * cc + ft * cs;
                pc[r] = ct;
                ph[r] = ot * tanhf(ct);
            }
            *(float4*)&out[gbase + q * 4] = hv;
            *(float4*)&out[(size_t)B_DIM * H_DIM + gbase + q * 4] = cv;
        }
    }
}

// -------- merged fp16 convert + fragment-major relayout pre-pass (ONE launch) --------
__global__ void __launch_bounds__(256) cvt_all_kernel(
    const float* __restrict__ core_input, const float* __restrict__ h_state,
    const float* __restrict__ concept,
    const float* __restrict__ W_in, const float* __restrict__ W_st,
    const float* __restrict__ W_ci, const float* __restrict__ W_cs) {
    int bid = blockIdx.x;
    if (bid < 1536) {   // A-type: 512 blocks per tensor
        int t = bid / 512;
        const float* src = (t == 0) ? core_input : (t == 1) ? h_state : concept;
        uint4* dst = (uint4*)((t == 0) ? hA_core : (t == 1) ? hA_h : hA_concept);
        int ldk = (t == 2) ? 1000 : 1024;
        int i = (bid - t * 512) * 256 + threadIdx.x;
        int lane = i & 31, ks = (i >> 5) & 3, kc = (i >> 7) & 15, mt = i >> 11;
        int gid = lane >> 2, ctid = lane & 3;
        int m = mt * 16 + gid;
        int k = kc * 64 + ks * 16 + 2 * ctid;
        __half2 p[4];
#pragma unroll
        for (int q = 0; q < 4; q++) {
            int mm = m + 8 * (q & 1);
            int kk = k + 8 * (q >> 1);
            float x0 = (kk < ldk)     ? src[(size_t)mm * ldk + kk]     : 0.0f;
            float x1 = (kk + 1 < ldk) ? src[(size_t)mm * ldk + kk + 1] : 0.0f;
            p[q] = __floats2half2_rn(x0, x1);
        }
        dst[i] = *(const uint4*)p;
    } else {            // W-type: 4096 blocks per tensor
        int b2 = bid - 1536;
        int t = b2 >> 12;
        const float* src = (t == 0) ? W_in : (t == 1) ? W_st : (t == 2) ? W_ci : W_cs;
        uint2* dst = (uint2*)((t == 0) ? hW_in : (t == 1) ? hW_st
                              : (t == 2) ? hW_ci : hW_cs);
        int ldk = (t >= 2) ? 1000 : 1024;
        int i = (b2 & 4095) * 256 + threadIdx.x;
        int lane = i & 31, ks = (i >> 5) & 3, kc = (i >> 7) & 15, nt = i >> 11;
        int gid = lane >> 2, ctid = lane & 3;
        int n = nt * 8 + gid;
        int k = kc * 64 + ks * 16 + 2 * ctid;
        __half2 p[2];
#pragma unroll
        for (int q = 0; q < 2; q++) {
            int kk = k + 8 * q;
            float x0 = (kk < ldk)     ? src[(size_t)n * ldk + kk]     : 0.0f;
            float x1 = (kk + 1 < ldk) ? src[(size_t)n * ldk + kk + 1] : 0.0f;
            p[q] = __floats2half2_rn(x0, x1);
        }
        dst[i] = *(const uint2*)p;
    }
}

extern "C" void kernel_launch(void* const* d_in, const int* in_sizes, int n_in,
                              void* d_out, int out_size) {
    const float* core_input = (const float*)d_in[0];
    const float* h_state    = (const float*)d_in[1];
    const float* c_state    = (const float*)d_in[2];
    const float* concept    = (const float*)d_in[3];
    const float* W_in       = (const float*)d_in[4];
    const float* W_st       = (const float*)d_in[5];
    const float* W_ci       = (const float*)d_in[6];
    const float* W_cs       = (const float*)d_in[7];
    float* out = (float*)d_out;

    static bool configured = false;
    if (!configured) {
        cudaFuncSetAttribute(scn_mma_kernel,
                             cudaFuncAttributeMaxDynamicSharedMemorySize, SMEM_BYTES);
        configured = true;
    }

    cvt_all_kernel<<<1536 + 4 * 4096, 256>>>(core_input, h_state, concept,
                                             W_in, W_st, W_ci, W_cs);

    dim3 grid(64, 8);   // 64 hcol tiles x 8 batch tiles = 512 CTAs (3/SM)
    scn_mma_kernel<<<grid, 256, SMEM_BYTES>>>(c_state, out);
}

// round 17
// speedup vs baseline: 1.1947x; 1.1947x over previous
#include <cuda_runtime.h>
#include <cuda_fp16.h>
#include <cstdint>
#include <math.h>

#define B_DIM 1024
#define H_DIM 1024
#define HIDS 68
#define EPI_SMEM (128 * HIDS * 4)   // 34816 B, epilogue staging only

// fp16 fragment-major operands (K padded 1000 -> 1024 with zeros)
// A: [mt(64)][kc(16)][ks(4)][lane(32)][8 halves]   (uint4 granules)
// W: [nt(512)][kc(16)][ks(4)][lane(32)][4 halves]  (uint2 granules)
__device__ __half hA_core[B_DIM * 1024];
__device__ __half hA_h[B_DIM * 1024];
__device__ __half hA_concept[B_DIM * 1024];
__device__ __half hW_in[4 * H_DIM * 1024];
__device__ __half hW_st[4 * H_DIM * 1024];
__device__ __half hW_ci[4 * H_DIM * 1024];
__device__ __half hW_cs[4 * H_DIM * 1024];
// inter-phase f32 accumulator spills (bit-exact round trip)
__device__ float g_xi[B_DIM * 4 * H_DIM];
__device__ float g_hs[B_DIM * 4 * H_DIM];
__device__ float g_gi[B_DIM * 4 * H_DIM];

__device__ __forceinline__ void mma16(float* d, const uint32_t* a, const uint32_t* b) {
    asm volatile(
        "mma.sync.aligned.m16n8k16.row.col.f32.f16.f16.f32 "
        "{%0,%1,%2,%3}, {%4,%5,%6,%7}, {%8,%9}, {%0,%1,%2,%3};"
        : "+f"(d[0]), "+f"(d[1]), "+f"(d[2]), "+f"(d[3])
        : "r"(a[0]), "r"(a[1]), "r"(a[2]), "r"(a[3]), "r"(b[0]), "r"(b[1]));
}

// One K=64 chunk, warp tile 32(M) x 32(N), fragments straight from gmem.
// aoff0/aoff1: uint4 base offsets (incl. lane) for the two m16-blocks at kc=0.
// boff[nt]:    uint2 base offsets (incl. lane) for the four n8-blocks at kc=0.
// Per-kc strides: A 128 uint4, B 128 uint2; per-ks strides: A 32 uint4, B 32 uint2.
__device__ __forceinline__ void gchunk(const uint4* __restrict__ A,
                                       const uint2* __restrict__ B,
                                       float (&acc)[32],
                                       size_t aoff0, size_t aoff1,
                                       const size_t (&boff)[4], int kc) {
    uint4 a[2][4];
    uint2 b[4][4];
    const size_t ak = (size_t)kc * 128;
#pragma unroll
    for (int ks = 0; ks < 4; ks++) {
        a[0][ks] = A[aoff0 + ak + ks * 32];
        a[1][ks] = A[aoff1 + ak + ks * 32];
    }
#pragma unroll
    for (int nt = 0; nt < 4; nt++)
#pragma unroll
        for (int ks = 0; ks < 4; ks++)
            b[nt][ks] = B[boff[nt] + ak + ks * 32];
    // identical MMA order to the smem version (bit-identical accumulation)
#pragma unroll
    for (int ks = 0; ks < 4; ks++)
#pragma unroll
        for (int mt = 0; mt < 2; mt++)
#pragma unroll
            for (int nt = 0; nt < 4; nt++)
                mma16(&acc[(mt * 4 + nt) * 4], (const uint32_t*)&a[mt][ks],
                      (const uint32_t*)&b[nt][ks]);
}

__global__ void __launch_bounds__(256, 2) scn_mma_kernel(
    const float* __restrict__ c_state, float* __restrict__ out) {
    extern __shared__ char smc[];
    const int tid = threadIdx.x, lane = tid & 31, wid = tid >> 5;
    const int gid = lane >> 2, ctid = lane & 3;
    const int wm = wid >> 1, wn = wid & 1;       // warp grid 4(M) x 2(N)
    const int hcol0 = blockIdx.x * 16;           // 16 h-cols x 4 sections = N 64
    const int brow0 = blockIdx.y * 128;
    const int cta = blockIdx.y * 64 + blockIdx.x;

    // A m16-blocks for this warp: by*8 + wm*2 + {0,1}
    const size_t aoff0 = ((size_t)(blockIdx.y * 8 + wm * 2)     * 16) * 128 + lane;
    const size_t aoff1 = ((size_t)(blockIdx.y * 8 + wm * 2 + 1) * 16) * 128 + lane;
    // B n8-blocks: local nb = wn*4 + nt -> global ntg = sec*128 + bx*2 + jb
    size_t boff[4];
#pragma unroll
    for (int nt = 0; nt < 4; nt++) {
        int nb = wn * 4 + nt;
        int ntg = ((nb >> 1) << 7) + blockIdx.x * 2 + (nb & 1);
        boff[nt] = ((size_t)ntg * 16) * 128 + lane;
    }

    const size_t fragbase = ((size_t)(cta * 8 + wid) * 8) * 32 + lane;

    {   // phase 0: xi = core @ W_in -> spill
        float acc[32] = {};
        const uint4* A = (const uint4*)hA_core;
        const uint2* B = (const uint2*)hW_in;
#pragma unroll 2
        for (int kc = 0; kc < 16; kc++) gchunk(A, B, acc, aoff0, aoff1, boff, kc);
        float4* sp = (float4*)g_xi;
#pragma unroll
        for (int t = 0; t < 8; t++)
            sp[fragbase + (size_t)t * 32] =
                make_float4(acc[t*4], acc[t*4+1], acc[t*4+2], acc[t*4+3]);
    }
    {   // phase 1: hs = h @ W_st -> spill
        float acc[32] = {};
        const uint4* A = (const uint4*)hA_h;
        const uint2* B = (const uint2*)hW_st;
#pragma unroll 2
        for (int kc = 0; kc < 16; kc++) gchunk(A, B, acc, aoff0, aoff1, boff, kc);
        float4* sp = (float4*)g_hs;
#pragma unroll
        for (int t = 0; t < 8; t++)
            sp[fragbase + (size_t)t * 32] =
                make_float4(acc[t*4], acc[t*4+1], acc[t*4+2], acc[t*4+3]);
    }
    {   // phase 2: gi = concept @ W_ci -> spill
        float acc[32] = {};
        const uint4* A = (const uint4*)hA_concept;
        const uint2* B = (const uint2*)hW_ci;
#pragma unroll 2
        for (int kc = 0; kc < 16; kc++) gchunk(A, B, acc, aoff0, aoff1, boff, kc);
        float4* sp = (float4*)g_gi;
#pragma unroll
        for (int t = 0; t < 8; t++)
            sp[fragbase + (size_t)t * 32] =
                make_float4(acc[t*4], acc[t*4+1], acc[t*4+2], acc[t*4+3]);
    }
    // phase 3: gs = concept @ W_cs (kept in regs)
    float ags[32] = {};
    {
        const uint4* A = (const uint4*)hA_concept;
        const uint2* B = (const uint2*)hW_cs;
#pragma unroll 2
        for (int kc = 0; kc < 16; kc++) gchunk(A, B, ags, aoff0, aoff1, boff, kc);
    }

    // ---- fused epilogue: hidden = sigmoid(gi*xi + gs*hs) staged in smem ----
    float* hid = (float*)smc;   // 128 x HIDS floats
    {
        const float4* xs = (const float4*)g_xi;
        const float4* hs = (const float4*)g_hs;
        const float4* gs = (const float4*)g_gi;
#pragma unroll
        for (int t = 0; t < 8; t++) {
            float4 x4 = xs[fragbase + (size_t)t * 32];
            float4 h4 = hs[fragbase + (size_t)t * 32];
            float4 g4 = gs[fragbase + (size_t)t * 32];
            const float zx[4] = {x4.x, x4.y, x4.z, x4.w};
            const float zh[4] = {h4.x, h4.y, h4.z, h4.w};
            const float zg[4] = {g4.x, g4.y, g4.z, g4.w};
            int mt = t >> 2, nt = t & 3;
#pragma unroll
            for (int c = 0; c < 4; c++) {
                float z = zg[c] * zx[c] + ags[t * 4 + c] * zh[c];
                int m = wm * 32 + mt * 16 + gid + ((c >> 1) ? 8 : 0);
                int n = wn * 32 + nt * 8 + ctid * 2 + (c & 1);   // n in 0..63
                hid[m * HIDS + n] = 1.0f / (1.0f + expf(-z));
            }
        }
    }
    __syncthreads();

    // ---- LSTM combine: hid[m][sec*16 + j], secs = i, f, o, c_cand ----
    {
        int m = tid >> 1;
        int j0 = (tid & 1) * 8;
        const float* row = hid + m * HIDS;
        size_t gbase = (size_t)(brow0 + m) * H_DIM + hcol0 + j0;
#pragma unroll
        for (int q = 0; q < 2; q++) {
            float4 hv, cv;
            float* ph = (float*)&hv;
            float* pc = (float*)&cv;
#pragma unroll
            for (int r = 0; r < 4; r++) {
                int j = j0 + q * 4 + r;
                float it = row[j];
                float ft = row[16 + j];
                float ot = row[32 + j];
                float cc = row[48 + j];
                float cs = c_state[gbase - j0 + j];
                float ct = it * cc + ft * cs;
                pc[r] = ct;
                ph[r] = ot * tanhf(ct);
            }
            *(float4*)&out[gbase + q * 4] = hv;
            *(float4*)&out[(size_t)B_DIM * H_DIM + gbase + q * 4] = cv;
        }
    }
}

// -------- merged fp16 convert + fragment-major relayout pre-pass (ONE launch) --------
__global__ void __launch_bounds__(256) cvt_all_kernel(
    const float* __restrict__ core_input, const float* __restrict__ h_state,
    const float* __restrict__ concept,
    const float* __restrict__ W_in, const float* __restrict__ W_st,
    const float* __restrict__ W_ci, const float* __restrict__ W_cs) {
    int bid = blockIdx.x;
    if (bid < 1536) {   // A-type: 512 blocks per tensor
        int t = bid / 512;
        const float* src = (t == 0) ? core_input : (t == 1) ? h_state : concept;
        uint4* dst = (uint4*)((t == 0) ? hA_core : (t == 1) ? hA_h : hA_concept);
        int ldk = (t == 2) ? 1000 : 1024;
        int i = (bid - t * 512) * 256 + threadIdx.x;
        int lane = i & 31, ks = (i >> 5) & 3, kc = (i >> 7) & 15, mt = i >> 11;
        int gid = lane >> 2, ctid = lane & 3;
        int m = mt * 16 + gid;
        int k = kc * 64 + ks * 16 + 2 * ctid;
        __half2 p[4];
#pragma unroll
        for (int q = 0; q < 4; q++) {
            int mm = m + 8 * (q & 1);
            int kk = k + 8 * (q >> 1);
            float x0 = (kk < ldk)     ? src[(size_t)mm * ldk + kk]     : 0.0f;
            float x1 = (kk + 1 < ldk) ? src[(size_t)mm * ldk + kk + 1] : 0.0f;
            p[q] = __floats2half2_rn(x0, x1);
        }
        dst[i] = *(const uint4*)p;
    } else {            // W-type: 4096 blocks per tensor
        int b2 = bid - 1536;
        int t = b2 >> 12;
        const float* src = (t == 0) ? W_in : (t == 1) ? W_st : (t == 2) ? W_ci : W_cs;
        uint2* dst = (uint2*)((t == 0) ? hW_in : (t == 1) ? hW_st
                              : (t == 2) ? hW_ci : hW_cs);
        int ldk = (t >= 2) ? 1000 : 1024;
        int i = (b2 & 4095) * 256 + threadIdx.x;
        int lane = i & 31, ks = (i >> 5) & 3, kc = (i >> 7) & 15, nt = i >> 11;
        int gid = lane >> 2, ctid = lane & 3;
        int n = nt * 8 + gid;
        int k = kc * 64 + ks * 16 + 2 * ctid;
        __half2 p[2];
#pragma unroll
        for (int q = 0; q < 2; q++) {
            int kk = k + 8 * q;
            float x0 = (kk < ldk)     ? src[(size_t)n * ldk + kk]     : 0.0f;
            float x1 = (kk + 1 < ldk) ? src[(size_t)n * ldk + kk + 1] : 0.0f;
            p[q] = __floats2half2_rn(x0, x1);
        }
        dst[i] = *(const uint2*)p;
    }
}

extern "C" void kernel_launch(void* const* d_in, const int* in_sizes, int n_in,
                              void* d_out, int out_size) {
    const float* core_input = (const float*)d_in[0];
    const float* h_state    = (const float*)d_in[1];
    const float* c_state    = (const float*)d_in[2];
    const float* concept    = (const float*)d_in[3];
    const float* W_in       = (const float*)d_in[4];
    const float* W_st       = (const float*)d_in[5];
    const float* W_ci       = (const float*)d_in[6];
    const float* W_cs       = (const float*)d_in[7];
    float* out = (float*)d_out;

    cvt_all_kernel<<<1536 + 4 * 4096, 256>>>(core_input, h_state, concept,
                                             W_in, W_st, W_ci, W_cs);

    dim3 grid(64, 8);   // 64 hcol tiles x 8 batch tiles = 512 CTAs
    scn_mma_kernel<<<grid, 256, EPI_SMEM>>>(c_state, out);
}